// round 4
// baseline (speedup 1.0000x reference)
#include <cuda_runtime.h>

// ---------------------------------------------------------------------------
// QuantumBranch R2: quadratic-form circuit + sum(q)=1 folds + cooperative
// epilogue with no staging buffer.
//   setup_kernel: builds V (16x16 unitary w/ phases folded), then
//     D_w[m][n] coefficients (z_w = sum D*PP[m]*QQ[n]), LayerNorm folds:
//     M''' (variance quadform incl. v, c, eps), w' = (w+b)*gamma, beta.
//   qmain: per-thread element -> PP/QQ pairs -> z via 100 LDS.128 quadform
//     -> exp -> qi = e * rsqrt(e^T M''' e) -> warp-cooperative epilogue
//     (lane owns an output dim pair, constants in regs, STG.64 coalesced).
// ---------------------------------------------------------------------------

typedef unsigned long long u64;

__device__ float4 g_C[100];      // [m*10+n] = {D0,D1,D2,D3}
__device__ float4 g_epi[32][3];  // per dim-pair: {w0',w1'},{w2',w3'},{beta,pad}
__device__ float4 g_varM[4];     // M''' rows

__device__ __forceinline__ u64 pk2(float a, float b) {
    u64 r; asm("mov.b64 %0,{%1,%2};" : "=l"(r) : "f"(a), "f"(b)); return r;
}
__device__ __forceinline__ void upk2(u64 v, float& a, float& b) {
    asm("mov.b64 {%0,%1},%2;" : "=f"(a), "=f"(b) : "l"(v));
}
__device__ __forceinline__ u64 f2fma(u64 a, u64 b, u64 c) {
    u64 d; asm("fma.rn.f32x2 %0,%1,%2,%3;" : "=l"(d) : "l"(a), "l"(b), "l"(c)); return d;
}
__device__ __forceinline__ u64 f2mul(u64 a, u64 b) {
    u64 d; asm("mul.rn.f32x2 %0,%1,%2;" : "=l"(d) : "l"(a), "l"(b)); return d;
}

__device__ __forceinline__ float wsum(float v) {
    #pragma unroll
    for (int o = 16; o; o >>= 1) v += __shfl_xor_sync(0xffffffffu, v, o);
    return v;
}

// packed upper-triangle index tables (2 bits each): (u,v) pairs, u<=v
#define UTU_PACK ((1u<<8)|(1u<<10)|(1u<<12)|(2u<<14)|(2u<<16)|(3u<<18))
#define UTV_PACK ((1u<<2)|(2u<<4)|(3u<<6)|(1u<<8)|(2u<<10)|(3u<<12)|(2u<<14)|(3u<<16)|(3u<<18))

__global__ void setup_kernel(const float* __restrict__ wts,
                             const float* __restrict__ W,
                             const float* __restrict__ b,
                             const float* __restrict__ gm,
                             const float* __restrict__ bt)
{
    __shared__ float2 sv[16][16];   // [col j][row i] = V[i][j]
    int tid = threadIdx.x;

    // ---- warp0 lanes 0..15: build V column j = tid ----
    if (tid < 16) {
        int j = tid;
        float2 st[16];
        #pragma unroll
        for (int k = 0; k < 16; k++) st[k] = make_float2(k == j ? 1.f : 0.f, 0.f);

        #pragma unroll
        for (int l = 0; l < 2; l++) {
            #pragma unroll
            for (int w = 0; w < 4; w++) {
                const float* g = wts + (l * 4 + w) * 3;
                float phi = g[0], th = g[1], om = g[2];
                float a = 0.5f * (phi + om), bb = 0.5f * (phi - om), hh = 0.5f * th;
                float sa, ca, sb, cb, stt, ct;
                __sincosf(a, &sa, &ca);
                __sincosf(bb, &sb, &cb);
                __sincosf(hh, &stt, &ct);
                float2 g00 = make_float2( ca * ct, -sa * ct);
                float2 g01 = make_float2(-cb * stt, -sb * stt);
                float2 g10 = make_float2( cb * stt, -sb * stt);
                float2 g11 = make_float2( ca * ct,  sa * ct);
                int mask = 8 >> w;
                #pragma unroll
                for (int k = 0; k < 16; k++) {
                    if (!(k & mask)) {
                        int k1 = k | mask;
                        float2 A = st[k], Bv = st[k1];
                        float2 t0, t1;
                        t0.x = g00.x * A.x - g00.y * A.y + g01.x * Bv.x - g01.y * Bv.y;
                        t0.y = g00.x * A.y + g00.y * A.x + g01.x * Bv.y + g01.y * Bv.x;
                        t1.x = g10.x * A.x - g10.y * A.y + g11.x * Bv.x - g11.y * Bv.y;
                        t1.y = g10.x * A.y + g10.y * A.x + g11.x * Bv.y + g11.y * Bv.x;
                        st[k] = t0; st[k1] = t1;
                    }
                }
            }
            int r = (l == 0) ? 1 : 2;
            #pragma unroll
            for (int w = 0; w < 4; w++) {
                int mc = 8 >> w, mt = 8 >> ((w + r) & 3);
                #pragma unroll
                for (int k = 0; k < 16; k++) {
                    if ((k & mc) && !(k & mt)) {
                        float2 tmp = st[k]; st[k] = st[k | mt]; st[k | mt] = tmp;
                    }
                }
            }
        }
        int pop = __popc(j) & 3;
        #pragma unroll
        for (int k = 0; k < 16; k++) {
            float2 v = st[k], o;
            if      (pop == 0) o = v;
            else if (pop == 1) o = make_float2( v.y, -v.x);
            else if (pop == 2) o = make_float2(-v.x, -v.y);
            else               o = make_float2(-v.y,  v.x);
            sv[j][k] = o;
        }
    }

    // ---- warp1 (tid 32..63): LayerNorm fold constants ----
    if (tid >= 32) {
        int lane = tid - 32;
        const float inv64 = 1.f / 64.f;
        float wa[4], wb[4];
        #pragma unroll
        for (int i = 0; i < 4; i++) { wa[i] = W[lane * 4 + i]; wb[i] = W[(lane + 32) * 4 + i]; }
        float ba = b[lane], bbv = b[lane + 32];

        float cm[4];
        #pragma unroll
        for (int i = 0; i < 4; i++) cm[i] = wsum(wa[i] + wb[i]) * inv64;
        float bm = wsum(ba + bbv) * inv64;
        #pragma unroll
        for (int i = 0; i < 4; i++) { wa[i] -= cm[i]; wb[i] -= cm[i]; }
        ba -= bm; bbv -= bm;

        float M[4][4];
        #pragma unroll
        for (int i = 0; i < 4; i++) {
            #pragma unroll
            for (int k = 0; k < 4; k++) {
                if (k >= i) {
                    float v = wsum(wa[i] * wa[k] + wb[i] * wb[k]) * inv64;
                    M[i][k] = v; M[k][i] = v;
                }
            }
        }
        float vv[4];
        #pragma unroll
        for (int i = 0; i < 4; i++) vv[i] = wsum(wa[i] * ba + wb[i] * bbv) * (2.f * inv64);
        float vc = wsum(ba * ba + bbv * bbv) * inv64;

        if (lane == 0) {
            // M''' = M + (v_i+v_k)/2 + c + eps   (uses sum(q)=1)
            #pragma unroll
            for (int i = 0; i < 4; i++) {
                float4 row;
                row.x = M[i][0] + 0.5f * (vv[i] + vv[0]) + vc + 1e-5f;
                row.y = M[i][1] + 0.5f * (vv[i] + vv[1]) + vc + 1e-5f;
                row.z = M[i][2] + 0.5f * (vv[i] + vv[2]) + vc + 1e-5f;
                row.w = M[i][3] + 0.5f * (vv[i] + vv[3]) + vc + 1e-5f;
                g_varM[i] = row;
            }
        }

        float ga = gm[lane], gb = gm[lane + 32];
        float bea = bt[lane], beb = bt[lane + 32];
        float* e = (float*)g_epi;
        {   // dims [0,64): each dim d -> pair p=d>>1, parity d&1
            int d = lane, p = d >> 1, par = d & 1;
            float* ep = e + p * 12;
            // w' = (w + b)*gamma   (bgg folded via sum(q)=1)
            ep[0 + par] = (wa[0] + ba) * ga; ep[2 + par] = (wa[1] + ba) * ga;
            ep[4 + par] = (wa[2] + ba) * ga; ep[6 + par] = (wa[3] + ba) * ga;
            ep[8 + par] = bea;               ep[10 + par] = 0.f;
        }
        {
            int d = lane + 32, p = d >> 1, par = d & 1;
            float* ep = e + p * 12;
            ep[0 + par] = (wb[0] + bbv) * gb; ep[2 + par] = (wb[1] + bbv) * gb;
            ep[4 + par] = (wb[2] + bbv) * gb; ep[6 + par] = (wb[3] + bbv) * gb;
            ep[8 + par] = beb;                ep[10 + par] = 0.f;
        }
    }

    __syncthreads();

    // ---- all 64 threads: D_w[m][n] coefficients ----
    // z_w = sum_{i} s_w(i) p_i = r^T A_w r,  r = P (x) Q  (Kronecker)
    // D folds the pair symmetry multiplicities.
    for (int t = tid; t < 400; t += 64) {
        int w = t & 3, mn = t >> 2;
        int m = mn / 10, n = mn % 10;
        int a = (UTU_PACK >> (2 * m)) & 3, c = (UTV_PACK >> (2 * m)) & 3;
        int bq = (UTU_PACK >> (2 * n)) & 3, d = (UTV_PACK >> (2 * n)) & 3;
        int shift = 3 - w;

        int j1 = 4 * a + bq, k1 = 4 * c + d;
        float R1 = 0.f;
        #pragma unroll
        for (int i = 0; i < 16; i++) {
            float sg = ((i >> shift) & 1) ? -1.f : 1.f;
            R1 += sg * (sv[j1][i].x * sv[k1][i].x + sv[j1][i].y * sv[k1][i].y);
        }
        float Dv;
        if (a == c && bq == d) {
            Dv = R1;
        } else if (a < c && bq < d) {
            int j2 = 4 * a + d, k2 = 4 * c + bq;
            float R2 = 0.f;
            #pragma unroll
            for (int i = 0; i < 16; i++) {
                float sg = ((i >> shift) & 1) ? -1.f : 1.f;
                R2 += sg * (sv[j2][i].x * sv[k2][i].x + sv[j2][i].y * sv[k2][i].y);
            }
            Dv = 2.f * (R1 + R2);
        } else {
            Dv = 2.f * R1;
        }
        ((float*)g_C)[mn * 4 + w] = Dv;
    }
}

__global__ __launch_bounds__(128, 5) void qmain(const float4* __restrict__ x4,
                                                u64* __restrict__ outq)
{
    __shared__ float4 sC[100];
    __shared__ float4 sM[4];
    __shared__ ulonglong2 sQ[128][2];   // per element: dup-packed qi0..qi3

    int tid = threadIdx.x;
    if (tid < 100)      sC[tid] = g_C[tid];
    else if (tid < 104) sM[tid - 100] = g_varM[tid - 100];

    int lane = tid & 31, w = tid >> 5;
    // per-lane output-dim-pair constants (stay in registers)
    const ulonglong2* ep2 = (const ulonglong2*)(&g_epi[lane][0]);
    ulonglong2 eA = ep2[0], eB = ep2[1], eC = ep2[2];
    u64 W0 = eA.x, W1 = eA.y, W2 = eB.x, W3 = eB.y, BETA = eC.x;
    __syncthreads();

    int idx = blockIdx.x * 128 + tid;
    float4 xv = x4[idx];

    // tanh via exp (accurate), half-angle sincos
    float cc[4], ss[4];
    {
        float xs[4] = {xv.x, xv.y, xv.z, xv.w};
        #pragma unroll
        for (int q = 0; q < 4; q++) {
            float e  = __expf(2.f * xs[q]);
            float th = __fdividef(e - 1.f, e + 1.f);
            __sincosf(th * 1.5707963267948966f, &ss[q], &cc[q]);
        }
    }
    float P0 = cc[0]*cc[1], P1 = cc[0]*ss[1], P2 = ss[0]*cc[1], P3 = ss[0]*ss[1];
    float Q0 = cc[2]*cc[3], Q1 = cc[2]*ss[3], Q2 = ss[2]*cc[3], Q3 = ss[2]*ss[3];

    // symmetric pair products, dup-packed for f32x2
    u64 PPd[10], QQd[10];
    {
        float pv0=P0*P0, pv1=P0*P1, pv2=P0*P2, pv3=P0*P3, pv4=P1*P1,
              pv5=P1*P2, pv6=P1*P3, pv7=P2*P2, pv8=P2*P3, pv9=P3*P3;
        PPd[0]=pk2(pv0,pv0); PPd[1]=pk2(pv1,pv1); PPd[2]=pk2(pv2,pv2);
        PPd[3]=pk2(pv3,pv3); PPd[4]=pk2(pv4,pv4); PPd[5]=pk2(pv5,pv5);
        PPd[6]=pk2(pv6,pv6); PPd[7]=pk2(pv7,pv7); PPd[8]=pk2(pv8,pv8);
        PPd[9]=pk2(pv9,pv9);
        float qv0=Q0*Q0, qv1=Q0*Q1, qv2=Q0*Q2, qv3=Q0*Q3, qv4=Q1*Q1,
              qv5=Q1*Q2, qv6=Q1*Q3, qv7=Q2*Q2, qv8=Q2*Q3, qv9=Q3*Q3;
        QQd[0]=pk2(qv0,qv0); QQd[1]=pk2(qv1,qv1); QQd[2]=pk2(qv2,qv2);
        QQd[3]=pk2(qv3,qv3); QQd[4]=pk2(qv4,qv4); QQd[5]=pk2(qv5,qv5);
        QQd[6]=pk2(qv6,qv6); QQd[7]=pk2(qv7,qv7); QQd[8]=pk2(qv8,qv8);
        QQd[9]=pk2(qv9,qv9);
    }

    // z_w = sum_m PP[m] * sum_n D_w[m][n] QQ[n]   (packed pairs z01, z23)
    u64 z01, z23;
    #pragma unroll
    for (int m = 0; m < 10; m++) {
        const ulonglong2* cm = (const ulonglong2*)(&sC[m * 10]);
        ulonglong2 v0 = cm[0];
        u64 T01 = f2mul(v0.x, QQd[0]);
        u64 T23 = f2mul(v0.y, QQd[0]);
        #pragma unroll
        for (int n = 1; n < 10; n++) {
            ulonglong2 v = cm[n];
            T01 = f2fma(v.x, QQd[n], T01);
            T23 = f2fma(v.y, QQd[n], T23);
        }
        if (m == 0) { z01 = f2mul(PPd[0], T01); z23 = f2mul(PPd[0], T23); }
        else        { z01 = f2fma(PPd[m], T01, z01); z23 = f2fma(PPd[m], T23, z23); }
    }
    float z0, z1, z2, z3;
    upk2(z01, z0, z1); upk2(z23, z2, z3);

    // softmax numerators (z in [-1,1]); normalization cancels against rsqrt
    float e0 = __expf(z0), e1 = __expf(z1), e2 = __expf(z2), e3 = __expf(z3);
    float4 M0 = sM[0], M1 = sM[1], M2 = sM[2], M3 = sM[3];
    float t0 = fmaf(M0.x, e0, fmaf(M0.y, e1, fmaf(M0.z, e2, M0.w * e3)));
    float t1 = fmaf(M1.x, e0, fmaf(M1.y, e1, fmaf(M1.z, e2, M1.w * e3)));
    float t2 = fmaf(M2.x, e0, fmaf(M2.y, e1, fmaf(M2.z, e2, M2.w * e3)));
    float t3 = fmaf(M3.x, e0, fmaf(M3.y, e1, fmaf(M3.z, e2, M3.w * e3)));
    float uu = fmaf(e0, t0, fmaf(e1, t1, fmaf(e2, t2, e3 * t3)));
    float rr = rsqrtf(uu);
    float qi0 = e0 * rr, qi1 = e1 * rr, qi2 = e2 * rr, qi3 = e3 * rr;

    sQ[tid][0] = make_ulonglong2(pk2(qi0, qi0), pk2(qi1, qi1));
    sQ[tid][1] = make_ulonglong2(pk2(qi2, qi2), pk2(qi3, qi3));
    __syncwarp();

    // cooperative epilogue: lane owns dims (2*lane, 2*lane+1) for all 32 elems
    size_t base = ((size_t)blockIdx.x * 128 + (size_t)w * 32) * 32 + lane;
    #pragma unroll
    for (int e = 0; e < 32; e++) {
        ulonglong2 a = sQ[w * 32 + e][0];
        ulonglong2 bq = sQ[w * 32 + e][1];
        u64 o = f2fma(W0, a.x, BETA);
        o = f2fma(W1, a.y, o);
        o = f2fma(W2, bq.x, o);
        o = f2fma(W3, bq.y, o);
        outq[base + (size_t)e * 32] = o;
    }
}

extern "C" void kernel_launch(void* const* d_in, const int* in_sizes, int n_in,
                              void* d_out, int out_size)
{
    const float* x   = (const float*)d_in[0];
    const float* wts = (const float*)d_in[1];
    const float* W   = (const float*)d_in[2];
    const float* b   = (const float*)d_in[3];
    const float* gm  = (const float*)d_in[4];
    const float* bt  = (const float*)d_in[5];
    int B = in_sizes[0] / 4;

    setup_kernel<<<1, 64>>>(wts, W, b, gm, bt);
    qmain<<<B / 128, 128>>>((const float4*)x, (u64*)d_out);
}